// round 16
// baseline (speedup 1.0000x reference)
#include <cuda_runtime.h>
#include <cuda_fp16.h>
#include <cstdint>

#define Bb    1024
#define Nn    512
#define Mm    128
#define CD    1024
#define ODIM  390
#define PODIM 448            // padded o width (7 x 64)
#define KS    8              // K-split for MMA GEMM
#define KCH2  (CD / KS)      // 128
#define BMt   128
#define BNt   64
#define BKt   32
#define APAD  40             // smem row stride in fp16 (32 + 8 pad)
#define CACHE_ROWS 128       // ntm: 8 rows per warp cached in smem

// scratch (__device__ global: allowed)
__device__ float g_part[KS * Bb * PODIM];             // 14.7 MB partials

// ---------------- helpers ----------------
__device__ __forceinline__ uint32_t smem_u32(const void* p) {
    uint32_t a;
    asm("{ .reg .u64 t; cvta.to.shared.u64 t, %1; cvt.u32.u64 %0, t; }"
        : "=r"(a) : "l"(p));
    return a;
}
__device__ __forceinline__ void ldsm_x4(uint32_t* r, uint32_t addr) {
    asm volatile("ldmatrix.sync.aligned.m8n8.x4.shared.b16 {%0,%1,%2,%3}, [%4];"
                 : "=r"(r[0]), "=r"(r[1]), "=r"(r[2]), "=r"(r[3]) : "r"(addr));
}
__device__ __forceinline__ void mma16816_f16(float* c, const uint32_t* a,
                                             const uint32_t* b) {
    asm volatile(
        "mma.sync.aligned.m16n8k16.row.col.f32.f16.f16.f32 "
        "{%0,%1,%2,%3}, {%4,%5,%6,%7}, {%8,%9}, {%0,%1,%2,%3};"
        : "+f"(c[0]), "+f"(c[1]), "+f"(c[2]), "+f"(c[3])
        : "r"(a[0]), "r"(a[1]), "r"(a[2]), "r"(a[3]), "r"(b[0]), "r"(b[1]));
}
__device__ __forceinline__ void cp_async16(uint32_t dst, const void* src) {
    asm volatile("cp.async.cg.shared.global [%0], [%1], 16;"
                 :: "r"(dst), "l"(src) : "memory");
}
__device__ __forceinline__ void cp_async_commit() {
    asm volatile("cp.async.commit_group;" ::: "memory");
}
__device__ __forceinline__ void cp_async_wait_all() {
    asm volatile("cp.async.wait_group 0;" ::: "memory");
}

// pack float4 -> 2x half2 (8 bytes)
__device__ __forceinline__ uint2 pack4h(float4 v) {
    __half2 p0 = __floats2half2_rn(v.x, v.y);
    __half2 p1 = __floats2half2_rn(v.z, v.w);
    return make_uint2(*(uint32_t*)&p0, *(uint32_t*)&p1);
}

// ---------------- Kernel 1: fp16 single-pass HMMA GEMM (unchanged) -----
__global__ __launch_bounds__(256) void fc_mma(const float* __restrict__ hid,
                                              const float* __restrict__ W) {
    __shared__ __half Ah[2][BMt][APAD];
    __shared__ __half Bh[2][BNt][APAD];

    const int tid = threadIdx.x, lane = tid & 31, wid = tid >> 5;
    const int b0 = blockIdx.x * BMt, j0 = blockIdx.y * BNt;
    const int k0 = blockIdx.z * KCH2;
    const int wm = wid & 3, wn = wid >> 2;

    const int arow[4] = {(tid + 0) >> 3, (tid + 256) >> 3,
                         (tid + 512) >> 3, (tid + 768) >> 3};
    const int aq = (tid & 7) * 4;
    const int brow0 = tid >> 3, brow1 = (tid + 256) >> 3;
    const bool bok0 = (j0 + brow0) < ODIM, bok1 = (j0 + brow1) < ODIM;

    float acc[2][4][4] = {};
    float4 pa[4], pb[2];

    #pragma unroll
    for (int rep = 0; rep < 4; rep++)
        pa[rep] = *(const float4*)(hid + (size_t)(b0 + arow[rep]) * CD + k0 + aq);
    pb[0] = bok0 ? *(const float4*)(W + (size_t)(j0 + brow0) * CD + k0 + aq)
                 : make_float4(0.f, 0.f, 0.f, 0.f);
    pb[1] = bok1 ? *(const float4*)(W + (size_t)(j0 + brow1) * CD + k0 + aq)
                 : make_float4(0.f, 0.f, 0.f, 0.f);
    #pragma unroll
    for (int rep = 0; rep < 4; rep++)
        *(uint2*)&Ah[0][arow[rep]][aq] = pack4h(pa[rep]);
    *(uint2*)&Bh[0][brow0][aq] = pack4h(pb[0]);
    *(uint2*)&Bh[0][brow1][aq] = pack4h(pb[1]);
    __syncthreads();

    int stage = 0;
    for (int kc = 0; kc < KCH2; kc += BKt) {
        const bool has_next = (kc + BKt) < KCH2;
        if (has_next) {
            const int kn = k0 + kc + BKt;
            #pragma unroll
            for (int rep = 0; rep < 4; rep++)
                pa[rep] = *(const float4*)(hid + (size_t)(b0 + arow[rep]) * CD + kn + aq);
            pb[0] = bok0 ? *(const float4*)(W + (size_t)(j0 + brow0) * CD + kn + aq)
                         : make_float4(0.f, 0.f, 0.f, 0.f);
            pb[1] = bok1 ? *(const float4*)(W + (size_t)(j0 + brow1) * CD + kn + aq)
                         : make_float4(0.f, 0.f, 0.f, 0.f);
        }

        #pragma unroll
        for (int s = 0; s < 2; s++) {
            uint32_t ah[2][4], bh[2][4];
            #pragma unroll
            for (int mb = 0; mb < 2; mb++) {
                int row = wm * 32 + mb * 16 + ((lane >> 3) & 1) * 8 + (lane & 7);
                int col = s * 16 + (lane >> 4) * 8;
                ldsm_x4(ah[mb], smem_u32(&Ah[stage][row][col]));
            }
            #pragma unroll
            for (int gb = 0; gb < 2; gb++) {
                int row = wn * 32 + gb * 16 + (lane >> 4) * 8 + (lane & 7);
                int col = s * 16 + ((lane >> 3) & 1) * 8;
                ldsm_x4(bh[gb], smem_u32(&Bh[stage][row][col]));
            }
            #pragma unroll
            for (int mb = 0; mb < 2; mb++)
                #pragma unroll
                for (int nb = 0; nb < 4; nb++) {
                    uint32_t bf[2] = {bh[nb >> 1][(nb & 1) * 2],
                                      bh[nb >> 1][(nb & 1) * 2 + 1]};
                    mma16816_f16(acc[mb][nb], ah[mb], bf);
                }
        }

        if (has_next) {
            const int ns = stage ^ 1;
            #pragma unroll
            for (int rep = 0; rep < 4; rep++)
                *(uint2*)&Ah[ns][arow[rep]][aq] = pack4h(pa[rep]);
            *(uint2*)&Bh[ns][brow0][aq] = pack4h(pb[0]);
            *(uint2*)&Bh[ns][brow1][aq] = pack4h(pb[1]);
            __syncthreads();
        }
        stage ^= 1;
    }

    float* __restrict__ dst = g_part + (size_t)blockIdx.z * Bb * PODIM;
    #pragma unroll
    for (int mb = 0; mb < 2; mb++)
        #pragma unroll
        for (int nb = 0; nb < 4; nb++) {
            int row0 = b0 + wm * 32 + mb * 16 + (lane >> 2);
            int col = j0 + wn * 32 + nb * 8 + (lane & 3) * 2;
            *(float2*)&dst[(size_t)row0 * PODIM + col] =
                make_float2(acc[mb][nb][0], acc[mb][nb][1]);
            *(float2*)&dst[(size_t)(row0 + 8) * PODIM + col] =
                make_float2(acc[mb][nb][2], acc[mb][nb][3]);
        }
}

// ---------------- NTM fused kernel (cp.async-staged cache rows) --------
__device__ __forceinline__ float sigmoidf_(float x) { return 1.f / (1.f + expf(-x)); }
__device__ __forceinline__ float softplusf_(float x) {
    return fmaxf(x, 0.f) + log1pf(expf(-fabsf(x)));
}

__device__ __forceinline__ float block_reduce_sum(float v, float* red) {
    int lane = threadIdx.x & 31, wid = threadIdx.x >> 5;
    #pragma unroll
    for (int off = 16; off; off >>= 1) v += __shfl_xor_sync(0xffffffffu, v, off);
    if (lane == 0) red[wid] = v;
    __syncthreads();
    if (wid == 0) {
        float x = (lane < 16) ? red[lane] : 0.f;
        #pragma unroll
        for (int off = 8; off; off >>= 1) x += __shfl_xor_sync(0xffffffffu, x, off);
        if (lane == 0) red[16] = x;
    }
    __syncthreads();
    float r = red[16];
    __syncthreads();
    return r;
}

__device__ __forceinline__ float block_reduce_max(float v, float* red) {
    int lane = threadIdx.x & 31, wid = threadIdx.x >> 5;
    #pragma unroll
    for (int off = 16; off; off >>= 1)
        v = fmaxf(v, __shfl_xor_sync(0xffffffffu, v, off));
    if (lane == 0) red[wid] = v;
    __syncthreads();
    if (wid == 0) {
        float x = (lane < 16) ? red[lane] : -3.4e38f;
        #pragma unroll
        for (int off = 8; off; off >>= 1)
            x = fmaxf(x, __shfl_xor_sync(0xffffffffu, x, off));
        if (lane == 0) red[16] = x;
    }
    __syncthreads();
    float r = red[16];
    __syncthreads();
    return r;
}

__global__ __launch_bounds__(512, 3) void ntm_fused(const float* __restrict__ w_pre,
                                                    const float* __restrict__ memory,
                                                    const float* __restrict__ bias,
                                                    float* __restrict__ out_w,
                                                    float* __restrict__ out_mem) {
    extern __shared__ float smem[];
    float* cache = smem;                           // CACHE_ROWS * 128 (64 KB)
    float* Ksm   = smem + CACHE_ROWS * Mm;         // 512
    float* wgsm  = Ksm + Nn;                       // 512
    float* k_e   = wgsm + Nn;                      // 128
    float* evec  = k_e + Mm;                       // 128
    float* avec  = evec + Mm;                      // 128
    float* red   = avec + Mm;                      // 32

    __shared__ float s_beta, s_g, s_s0, s_s1, s_s2, s_gamma, s_knorm;
    __shared__ float s_raw[3];

    const int b = blockIdx.x;
    const int tid = threadIdx.x;
    const int lane = tid & 31, wid = tid >> 5;
    const float* __restrict__ memb = memory + (size_t)b * Nn * Mm;
    const int n_base = wid * 32;

    // fire-and-forget: stage this warp's 8 cache rows via cp.async
    {
        uint32_t cbase = smem_u32(cache) + (uint32_t)(wid * 8) * 512u + (uint32_t)lane * 16u;
        const char* gbase = (const char*)(memb + (size_t)n_base * Mm) + lane * 16;
        #pragma unroll
        for (int r = 0; r < 8; r++)
            cp_async16(cbase + r * 512u, gbase + r * 512);
        cp_async_commit();
    }
    // prefetch w_pre early (consumed in phase 2)
    const float wpre = __ldg(&w_pre[(size_t)b * Nn + tid]);

    // ---- phase 0: reduce KS partials + activations ----
    if (tid < ODIM) {
        float v = bias[tid];
        #pragma unroll
        for (int z = 0; z < KS; z++)
            v += g_part[((size_t)z * Bb + b) * PODIM + tid];
        int j = tid;
        if (j < 128)            k_e[j] = v + 1e-16f;
        else if (j == 128)      s_beta = softplusf_(v);
        else if (j == 129)      s_g    = sigmoidf_(v);
        else if (j <= 132)      s_raw[j - 130] = v;
        else if (j == 133)      s_gamma = 1.f + softplusf_(v);
        else if (j < 262)       evec[j - 134] = sigmoidf_(v);
        else                    avec[j - 262] = v;
    }
    __syncthreads();
    if (tid == 0) {
        float x0 = s_raw[0], x1 = s_raw[1], x2 = s_raw[2];
        float mx = fmaxf(x0, fmaxf(x1, x2));
        float e0 = expf(x0 - mx), e1 = expf(x1 - mx), e2 = expf(x2 - mx);
        float inv = 1.f / (e0 + e1 + e2);
        s_s0 = e0 * inv; s_s1 = e1 * inv; s_s2 = e2 * inv;
    }
    {
        float v = (tid < Mm) ? k_e[tid] * k_e[tid] : 0.f;
        float ss = block_reduce_sum(v, red);
        if (tid == 0) s_knorm = sqrtf(ss);
        __syncthreads();
    }
    const float knorm = s_knorm;

    // ---- phase 1: cosine sim. 16 lanes per row ----
    {
        const int xh = lane & 15;
        const int half = lane >> 4;
        const float4 ka = *(const float4*)&k_e[xh * 4];
        const float4 kb = *(const float4*)&k_e[64 + xh * 4];

        // uncached rows first (offsets 8..31), 4 rows in flight
        #pragma unroll 1
        for (int i = 8; i < 32; i += 4) {
            const int n = n_base + i;
            const float* r0 = memb + (size_t)(n + half) * Mm;
            const float* r1 = memb + (size_t)(n + 2 + half) * Mm;
            float4 a0 = __ldg((const float4*)r0 + xh);
            float4 b0 = __ldg((const float4*)(r0 + 64) + xh);
            float4 a1 = __ldg((const float4*)r1 + xh);
            float4 b1 = __ldg((const float4*)(r1 + 64) + xh);

            #pragma unroll
            for (int p = 0; p < 2; p++) {
                float4 A = p ? a1 : a0;
                float4 B = p ? b1 : b0;
                float num = 0.f, ss = 0.f, x;
                x = A.x + 1e-16f; num = fmaf(x, ka.x, num); ss = fmaf(x, x, ss);
                x = A.y + 1e-16f; num = fmaf(x, ka.y, num); ss = fmaf(x, x, ss);
                x = A.z + 1e-16f; num = fmaf(x, ka.z, num); ss = fmaf(x, x, ss);
                x = A.w + 1e-16f; num = fmaf(x, ka.w, num); ss = fmaf(x, x, ss);
                x = B.x + 1e-16f; num = fmaf(x, kb.x, num); ss = fmaf(x, x, ss);
                x = B.y + 1e-16f; num = fmaf(x, kb.y, num); ss = fmaf(x, x, ss);
                x = B.z + 1e-16f; num = fmaf(x, kb.z, num); ss = fmaf(x, x, ss);
                x = B.w + 1e-16f; num = fmaf(x, kb.w, num); ss = fmaf(x, x, ss);
                #pragma unroll
                for (int off = 1; off <= 8; off <<= 1) {
                    num += __shfl_xor_sync(0xffffffffu, num, off);
                    ss  += __shfl_xor_sync(0xffffffffu, ss, off);
                }
                if (xh == 0) {
                    float denom = sqrtf(ss) * knorm;
                    Ksm[n + 2 * p + half] = num / fmaxf(denom, 1e-8f);
                }
            }
        }

        // cached rows (offsets 0..7): data staged in smem by cp.async
        cp_async_wait_all();
        __syncwarp();
        #pragma unroll 1
        for (int i = 0; i < 8; i += 4) {
            const int n = n_base + i;
            const float* c0 = cache + (size_t)(wid * 8 + i + half) * Mm;
            const float* c1 = cache + (size_t)(wid * 8 + i + 2 + half) * Mm;
            float4 a0 = *((const float4*)c0 + xh);
            float4 b0 = *((const float4*)(c0 + 64) + xh);
            float4 a1 = *((const float4*)c1 + xh);
            float4 b1 = *((const float4*)(c1 + 64) + xh);

            #pragma unroll
            for (int p = 0; p < 2; p++) {
                float4 A = p ? a1 : a0;
                float4 B = p ? b1 : b0;
                float num = 0.f, ss = 0.f, x;
                x = A.x + 1e-16f; num = fmaf(x, ka.x, num); ss = fmaf(x, x, ss);
                x = A.y + 1e-16f; num = fmaf(x, ka.y, num); ss = fmaf(x, x, ss);
                x = A.z + 1e-16f; num = fmaf(x, ka.z, num); ss = fmaf(x, x, ss);
                x = A.w + 1e-16f; num = fmaf(x, ka.w, num); ss = fmaf(x, x, ss);
                x = B.x + 1e-16f; num = fmaf(x, kb.x, num); ss = fmaf(x, x, ss);
                x = B.y + 1e-16f; num = fmaf(x, kb.y, num); ss = fmaf(x, x, ss);
                x = B.z + 1e-16f; num = fmaf(x, kb.z, num); ss = fmaf(x, x, ss);
                x = B.w + 1e-16f; num = fmaf(x, kb.w, num); ss = fmaf(x, x, ss);
                #pragma unroll
                for (int off = 1; off <= 8; off <<= 1) {
                    num += __shfl_xor_sync(0xffffffffu, num, off);
                    ss  += __shfl_xor_sync(0xffffffffu, ss, off);
                }
                if (xh == 0) {
                    float denom = sqrtf(ss) * knorm;
                    Ksm[n + 2 * p + half] = num / fmaxf(denom, 1e-8f);
                }
            }
        }
    }
    __syncthreads();

    // ---- phase 2 ----
    const int n = tid;
    float bk = s_beta * Ksm[n];
    float mx = block_reduce_max(bk, red);
    float p = expf(bk - mx);
    float psum = block_reduce_sum(p, red);
    float wc = p / psum;
    float g = s_g;
    float wg = g * wc + (1.f - g) * wpre;
    wgsm[n] = wg;
    __syncthreads();
    float wsh = s_s0 * wgsm[(n + Nn - 1) & (Nn - 1)]
              + s_s1 * wg
              + s_s2 * wgsm[(n + 1) & (Nn - 1)];
    float wsp = powf(wsh, s_gamma);
    float wsum = block_reduce_sum(wsp, red);
    float w = wsp / (wsum + 1e-16f);
    out_w[(size_t)b * Nn + n] = w;
    Ksm[n] = w;
    __syncthreads();

    // ---- phase 3 ----
    const float4 ev = *((const float4*)evec + lane);
    const float4 av = *((const float4*)avec + lane);
    float* __restrict__ omb = out_mem + (size_t)b * Nn * Mm;

    #pragma unroll 1
    for (int j = 8; j < 32; j += 4) {
        const int nr = n_base + j;
        float4 m0 = __ldcs((const float4*)(memb + (size_t)(nr + 0) * Mm) + lane);
        float4 m1 = __ldcs((const float4*)(memb + (size_t)(nr + 1) * Mm) + lane);
        float4 m2 = __ldcs((const float4*)(memb + (size_t)(nr + 2) * Mm) + lane);
        float4 m3 = __ldcs((const float4*)(memb + (size_t)(nr + 3) * Mm) + lane);
        #pragma unroll
        for (int qq = 0; qq < 4; qq++) {
            float4 mv = (qq == 0) ? m0 : (qq == 1) ? m1 : (qq == 2) ? m2 : m3;
            float wn = Ksm[nr + qq];
            float4 r;
            r.x = mv.x * (1.f - wn * ev.x) + wn * av.x;
            r.y = mv.y * (1.f - wn * ev.y) + wn * av.y;
            r.z = mv.z * (1.f - wn * ev.z) + wn * av.z;
            r.w = mv.w * (1.f - wn * ev.w) + wn * av.w;
            __stcs((float4*)(omb + (size_t)(nr + qq) * Mm) + lane, r);
        }
    }
    #pragma unroll 2
    for (int r8 = 0; r8 < 8; r8++) {
        const int nr = n_base + r8;
        float wn = Ksm[nr];
        float4 mv = *((const float4*)(cache + (size_t)(wid * 8 + r8) * Mm) + lane);
        float4 r;
        r.x = mv.x * (1.f - wn * ev.x) + wn * av.x;
        r.y = mv.y * (1.f - wn * ev.y) + wn * av.y;
        r.z = mv.z * (1.f - wn * ev.z) + wn * av.z;
        r.w = mv.w * (1.f - wn * ev.w) + wn * av.w;
        __stcs((float4*)(omb + (size_t)nr * Mm) + lane, r);
    }
}

// ------------------------------------------------------------------
extern "C" void kernel_launch(void* const* d_in, const int* in_sizes, int n_in,
                              void* d_out, int out_size) {
    const float* hid    = (const float*)d_in[0];
    const float* w_pre  = (const float*)d_in[1];
    const float* memory = (const float*)d_in[2];
    const float* W_fc   = (const float*)d_in[3];
    const float* b_fc   = (const float*)d_in[4];
    float* out = (float*)d_out;
    float* out_w   = out;
    float* out_mem = out + (size_t)Bb * Nn;

    const int ntm_smem = (CACHE_ROWS * Mm + Nn + Nn + Mm + Mm + Mm + 32) * 4;
    static bool attr_set = false;
    if (!attr_set) {
        cudaFuncSetAttribute(ntm_fused, cudaFuncAttributeMaxDynamicSharedMemorySize,
                             ntm_smem);
        attr_set = true;
    }

    fc_mma<<<dim3(Bb / BMt, PODIM / BNt, KS), 256>>>(hid, W_fc);
    ntm_fused<<<Bb, 512, ntm_smem>>>(w_pre, memory, b_fc, out_w, out_mem);
}

// round 17
// speedup vs baseline: 1.0196x; 1.0196x over previous
#include <cuda_runtime.h>
#include <cuda_fp16.h>
#include <cstdint>

#define Bb    1024
#define Nn    512
#define Mm    128
#define CD    1024
#define ODIM  390
#define PODIM 448            // padded o width (7 x 64)
#define KS    4              // K-split for MMA GEMM
#define KCH2  (CD / KS)      // 256
#define BMt   128
#define BNt   64
#define BKt   32
#define APAD  40             // smem row stride in fp16 (32 + 8 pad)
#define CACHE_ROWS 128       // ntm: 8 rows per warp cached in smem

// scratch (__device__ global: allowed)
__device__ float g_part[KS * Bb * PODIM];             // 7.3 MB partials

// ---------------- helpers ----------------
__device__ __forceinline__ uint32_t smem_u32(const void* p) {
    uint32_t a;
    asm("{ .reg .u64 t; cvta.to.shared.u64 t, %1; cvt.u32.u64 %0, t; }"
        : "=r"(a) : "l"(p));
    return a;
}
__device__ __forceinline__ void ldsm_x4(uint32_t* r, uint32_t addr) {
    asm volatile("ldmatrix.sync.aligned.m8n8.x4.shared.b16 {%0,%1,%2,%3}, [%4];"
                 : "=r"(r[0]), "=r"(r[1]), "=r"(r[2]), "=r"(r[3]) : "r"(addr));
}
__device__ __forceinline__ void mma16816_f16(float* c, const uint32_t* a,
                                             const uint32_t* b) {
    asm volatile(
        "mma.sync.aligned.m16n8k16.row.col.f32.f16.f16.f32 "
        "{%0,%1,%2,%3}, {%4,%5,%6,%7}, {%8,%9}, {%0,%1,%2,%3};"
        : "+f"(c[0]), "+f"(c[1]), "+f"(c[2]), "+f"(c[3])
        : "r"(a[0]), "r"(a[1]), "r"(a[2]), "r"(a[3]), "r"(b[0]), "r"(b[1]));
}
__device__ __forceinline__ void cp_async16(uint32_t dst, const void* src) {
    asm volatile("cp.async.cg.shared.global [%0], [%1], 16;"
                 :: "r"(dst), "l"(src) : "memory");
}
__device__ __forceinline__ void cp_async_commit() {
    asm volatile("cp.async.commit_group;" ::: "memory");
}
__device__ __forceinline__ void cp_async_wait_all() {
    asm volatile("cp.async.wait_group 0;" ::: "memory");
}

// pack float4 -> 2x half2 (8 bytes)
__device__ __forceinline__ uint2 pack4h(float4 v) {
    __half2 p0 = __floats2half2_rn(v.x, v.y);
    __half2 p1 = __floats2half2_rn(v.z, v.w);
    return make_uint2(*(uint32_t*)&p0, *(uint32_t*)&p1);
}

// ---------------- Kernel 1: fp16 single-pass HMMA GEMM -----------------
// CTA 128x64 tile; 8 warps in 4(m) x 2(n); each warp 32x32 out. KS=4.
__global__ __launch_bounds__(256) void fc_mma(const float* __restrict__ hid,
                                              const float* __restrict__ W) {
    __shared__ __half Ah[2][BMt][APAD];
    __shared__ __half Bh[2][BNt][APAD];

    const int tid = threadIdx.x, lane = tid & 31, wid = tid >> 5;
    const int b0 = blockIdx.x * BMt, j0 = blockIdx.y * BNt;
    const int k0 = blockIdx.z * KCH2;
    const int wm = wid & 3, wn = wid >> 2;

    const int arow[4] = {(tid + 0) >> 3, (tid + 256) >> 3,
                         (tid + 512) >> 3, (tid + 768) >> 3};
    const int aq = (tid & 7) * 4;
    const int brow0 = tid >> 3, brow1 = (tid + 256) >> 3;
    const bool bok0 = (j0 + brow0) < ODIM, bok1 = (j0 + brow1) < ODIM;

    float acc[2][4][4] = {};
    float4 pa[4], pb[2];

    #pragma unroll
    for (int rep = 0; rep < 4; rep++)
        pa[rep] = *(const float4*)(hid + (size_t)(b0 + arow[rep]) * CD + k0 + aq);
    pb[0] = bok0 ? *(const float4*)(W + (size_t)(j0 + brow0) * CD + k0 + aq)
                 : make_float4(0.f, 0.f, 0.f, 0.f);
    pb[1] = bok1 ? *(const float4*)(W + (size_t)(j0 + brow1) * CD + k0 + aq)
                 : make_float4(0.f, 0.f, 0.f, 0.f);
    #pragma unroll
    for (int rep = 0; rep < 4; rep++)
        *(uint2*)&Ah[0][arow[rep]][aq] = pack4h(pa[rep]);
    *(uint2*)&Bh[0][brow0][aq] = pack4h(pb[0]);
    *(uint2*)&Bh[0][brow1][aq] = pack4h(pb[1]);
    __syncthreads();

    int stage = 0;
    for (int kc = 0; kc < KCH2; kc += BKt) {
        const bool has_next = (kc + BKt) < KCH2;
        if (has_next) {
            const int kn = k0 + kc + BKt;
            #pragma unroll
            for (int rep = 0; rep < 4; rep++)
                pa[rep] = *(const float4*)(hid + (size_t)(b0 + arow[rep]) * CD + kn + aq);
            pb[0] = bok0 ? *(const float4*)(W + (size_t)(j0 + brow0) * CD + kn + aq)
                         : make_float4(0.f, 0.f, 0.f, 0.f);
            pb[1] = bok1 ? *(const float4*)(W + (size_t)(j0 + brow1) * CD + kn + aq)
                         : make_float4(0.f, 0.f, 0.f, 0.f);
        }

        #pragma unroll
        for (int s = 0; s < 2; s++) {
            uint32_t ah[2][4], bh[2][4];
            #pragma unroll
            for (int mb = 0; mb < 2; mb++) {
                int row = wm * 32 + mb * 16 + ((lane >> 3) & 1) * 8 + (lane & 7);
                int col = s * 16 + (lane >> 4) * 8;
                ldsm_x4(ah[mb], smem_u32(&Ah[stage][row][col]));
            }
            #pragma unroll
            for (int gb = 0; gb < 2; gb++) {
                int row = wn * 32 + gb * 16 + (lane >> 4) * 8 + (lane & 7);
                int col = s * 16 + ((lane >> 3) & 1) * 8;
                ldsm_x4(bh[gb], smem_u32(&Bh[stage][row][col]));
            }
            #pragma unroll
            for (int mb = 0; mb < 2; mb++)
                #pragma unroll
                for (int nb = 0; nb < 4; nb++) {
                    uint32_t bf[2] = {bh[nb >> 1][(nb & 1) * 2],
                                      bh[nb >> 1][(nb & 1) * 2 + 1]};
                    mma16816_f16(acc[mb][nb], ah[mb], bf);
                }
        }

        if (has_next) {
            const int ns = stage ^ 1;
            #pragma unroll
            for (int rep = 0; rep < 4; rep++)
                *(uint2*)&Ah[ns][arow[rep]][aq] = pack4h(pa[rep]);
            *(uint2*)&Bh[ns][brow0][aq] = pack4h(pb[0]);
            *(uint2*)&Bh[ns][brow1][aq] = pack4h(pb[1]);
            __syncthreads();
        }
        stage ^= 1;
    }

    float* __restrict__ dst = g_part + (size_t)blockIdx.z * Bb * PODIM;
    #pragma unroll
    for (int mb = 0; mb < 2; mb++)
        #pragma unroll
        for (int nb = 0; nb < 4; nb++) {
            int row0 = b0 + wm * 32 + mb * 16 + (lane >> 2);
            int col = j0 + wn * 32 + nb * 8 + (lane & 3) * 2;
            *(float2*)&dst[(size_t)row0 * PODIM + col] =
                make_float2(acc[mb][nb][0], acc[mb][nb][1]);
            *(float2*)&dst[(size_t)(row0 + 8) * PODIM + col] =
                make_float2(acc[mb][nb][2], acc[mb][nb][3]);
        }
}

// ---------------- NTM fused kernel ----------------
__device__ __forceinline__ float sigmoidf_(float x) { return 1.f / (1.f + expf(-x)); }
__device__ __forceinline__ float softplusf_(float x) {
    return fmaxf(x, 0.f) + log1pf(expf(-fabsf(x)));
}

__device__ __forceinline__ float block_reduce_sum(float v, float* red) {
    int lane = threadIdx.x & 31, wid = threadIdx.x >> 5;
    #pragma unroll
    for (int off = 16; off; off >>= 1) v += __shfl_xor_sync(0xffffffffu, v, off);
    if (lane == 0) red[wid] = v;
    __syncthreads();
    if (wid == 0) {
        float x = (lane < 16) ? red[lane] : 0.f;
        #pragma unroll
        for (int off = 8; off; off >>= 1) x += __shfl_xor_sync(0xffffffffu, x, off);
        if (lane == 0) red[16] = x;
    }
    __syncthreads();
    float r = red[16];
    __syncthreads();
    return r;
}

__device__ __forceinline__ float block_reduce_max(float v, float* red) {
    int lane = threadIdx.x & 31, wid = threadIdx.x >> 5;
    #pragma unroll
    for (int off = 16; off; off >>= 1)
        v = fmaxf(v, __shfl_xor_sync(0xffffffffu, v, off));
    if (lane == 0) red[wid] = v;
    __syncthreads();
    if (wid == 0) {
        float x = (lane < 16) ? red[lane] : -3.4e38f;
        #pragma unroll
        for (int off = 8; off; off >>= 1)
            x = fmaxf(x, __shfl_xor_sync(0xffffffffu, x, off));
        if (lane == 0) red[16] = x;
    }
    __syncthreads();
    float r = red[16];
    __syncthreads();
    return r;
}

__global__ __launch_bounds__(512, 3) void ntm_fused(const float* __restrict__ w_pre,
                                                    const float* __restrict__ memory,
                                                    const float* __restrict__ bias,
                                                    float* __restrict__ out_w,
                                                    float* __restrict__ out_mem) {
    extern __shared__ float smem[];
    float* cache = smem;                           // CACHE_ROWS * 128 (64 KB)
    float* Ksm   = smem + CACHE_ROWS * Mm;         // 512
    float* wgsm  = Ksm + Nn;                       // 512
    float* k_e   = wgsm + Nn;                      // 128
    float* evec  = k_e + Mm;                       // 128
    float* avec  = evec + Mm;                      // 128
    float* red   = avec + Mm;                      // 32

    __shared__ float s_beta, s_g, s_s0, s_s1, s_s2, s_gamma, s_knorm;
    __shared__ float s_raw[3];

    const int b = blockIdx.x;
    const int tid = threadIdx.x;
    const int lane = tid & 31, wid = tid >> 5;
    const float* __restrict__ memb = memory + (size_t)b * Nn * Mm;
    const int n_base = wid * 32;

    // fire-and-forget: stage this warp's 8 cache rows via cp.async
    {
        uint32_t cbase = smem_u32(cache) + (uint32_t)(wid * 8) * 512u + (uint32_t)lane * 16u;
        const char* gbase = (const char*)(memb + (size_t)n_base * Mm) + lane * 16;
        #pragma unroll
        for (int r = 0; r < 8; r++)
            cp_async16(cbase + r * 512u, gbase + r * 512);
        cp_async_commit();
    }
    // prefetch w_pre early (consumed in phase 2)
    const float wpre = __ldg(&w_pre[(size_t)b * Nn + tid]);

    // ---- phase 0: reduce KS partials (read-once: evict-first) + act ----
    if (tid < ODIM) {
        float v = bias[tid];
        #pragma unroll
        for (int z = 0; z < KS; z++)
            v += __ldcs(&g_part[((size_t)z * Bb + b) * PODIM + tid]);
        int j = tid;
        if (j < 128)            k_e[j] = v + 1e-16f;
        else if (j == 128)      s_beta = softplusf_(v);
        else if (j == 129)      s_g    = sigmoidf_(v);
        else if (j <= 132)      s_raw[j - 130] = v;
        else if (j == 133)      s_gamma = 1.f + softplusf_(v);
        else if (j < 262)       evec[j - 134] = sigmoidf_(v);
        else                    avec[j - 262] = v;
    }
    __syncthreads();
    if (tid == 0) {
        float x0 = s_raw[0], x1 = s_raw[1], x2 = s_raw[2];
        float mx = fmaxf(x0, fmaxf(x1, x2));
        float e0 = expf(x0 - mx), e1 = expf(x1 - mx), e2 = expf(x2 - mx);
        float inv = 1.f / (e0 + e1 + e2);
        s_s0 = e0 * inv; s_s1 = e1 * inv; s_s2 = e2 * inv;
    }
    {
        float v = (tid < Mm) ? k_e[tid] * k_e[tid] : 0.f;
        float ss = block_reduce_sum(v, red);
        if (tid == 0) s_knorm = sqrtf(ss);
        __syncthreads();
    }
    const float knorm = s_knorm;

    // ---- phase 1: cosine sim. 16 lanes per row ----
    {
        const int xh = lane & 15;
        const int half = lane >> 4;
        const float4 ka = *(const float4*)&k_e[xh * 4];
        const float4 kb = *(const float4*)&k_e[64 + xh * 4];

        // uncached rows first (offsets 8..31), 4 rows in flight
        #pragma unroll 1
        for (int i = 8; i < 32; i += 4) {
            const int n = n_base + i;
            const float* r0 = memb + (size_t)(n + half) * Mm;
            const float* r1 = memb + (size_t)(n + 2 + half) * Mm;
            float4 a0 = __ldg((const float4*)r0 + xh);
            float4 b0 = __ldg((const float4*)(r0 + 64) + xh);
            float4 a1 = __ldg((const float4*)r1 + xh);
            float4 b1 = __ldg((const float4*)(r1 + 64) + xh);

            #pragma unroll
            for (int p = 0; p < 2; p++) {
                float4 A = p ? a1 : a0;
                float4 B = p ? b1 : b0;
                float num = 0.f, ss = 0.f, x;
                x = A.x + 1e-16f; num = fmaf(x, ka.x, num); ss = fmaf(x, x, ss);
                x = A.y + 1e-16f; num = fmaf(x, ka.y, num); ss = fmaf(x, x, ss);
                x = A.z + 1e-16f; num = fmaf(x, ka.z, num); ss = fmaf(x, x, ss);
                x = A.w + 1e-16f; num = fmaf(x, ka.w, num); ss = fmaf(x, x, ss);
                x = B.x + 1e-16f; num = fmaf(x, kb.x, num); ss = fmaf(x, x, ss);
                x = B.y + 1e-16f; num = fmaf(x, kb.y, num); ss = fmaf(x, x, ss);
                x = B.z + 1e-16f; num = fmaf(x, kb.z, num); ss = fmaf(x, x, ss);
                x = B.w + 1e-16f; num = fmaf(x, kb.w, num); ss = fmaf(x, x, ss);
                #pragma unroll
                for (int off = 1; off <= 8; off <<= 1) {
                    num += __shfl_xor_sync(0xffffffffu, num, off);
                    ss  += __shfl_xor_sync(0xffffffffu, ss, off);
                }
                if (xh == 0) {
                    float denom = sqrtf(ss) * knorm;
                    Ksm[n + 2 * p + half] = num / fmaxf(denom, 1e-8f);
                }
            }
        }

        // cached rows (offsets 0..7): data staged in smem by cp.async
        cp_async_wait_all();
        __syncwarp();
        #pragma unroll 1
        for (int i = 0; i < 8; i += 4) {
            const int n = n_base + i;
            const float* c0 = cache + (size_t)(wid * 8 + i + half) * Mm;
            const float* c1 = cache + (size_t)(wid * 8 + i + 2 + half) * Mm;
            float4 a0 = *((const float4*)c0 + xh);
            float4 b0 = *((const float4*)(c0 + 64) + xh);
            float4 a1 = *((const float4*)c1 + xh);
            float4 b1 = *((const float4*)(c1 + 64) + xh);

            #pragma unroll
            for (int p = 0; p < 2; p++) {
                float4 A = p ? a1 : a0;
                float4 B = p ? b1 : b0;
                float num = 0.f, ss = 0.f, x;
                x = A.x + 1e-16f; num = fmaf(x, ka.x, num); ss = fmaf(x, x, ss);
                x = A.y + 1e-16f; num = fmaf(x, ka.y, num); ss = fmaf(x, x, ss);
                x = A.z + 1e-16f; num = fmaf(x, ka.z, num); ss = fmaf(x, x, ss);
                x = A.w + 1e-16f; num = fmaf(x, ka.w, num); ss = fmaf(x, x, ss);
                x = B.x + 1e-16f; num = fmaf(x, kb.x, num); ss = fmaf(x, x, ss);
                x = B.y + 1e-16f; num = fmaf(x, kb.y, num); ss = fmaf(x, x, ss);
                x = B.z + 1e-16f; num = fmaf(x, kb.z, num); ss = fmaf(x, x, ss);
                x = B.w + 1e-16f; num = fmaf(x, kb.w, num); ss = fmaf(x, x, ss);
                #pragma unroll
                for (int off = 1; off <= 8; off <<= 1) {
                    num += __shfl_xor_sync(0xffffffffu, num, off);
                    ss  += __shfl_xor_sync(0xffffffffu, ss, off);
                }
                if (xh == 0) {
                    float denom = sqrtf(ss) * knorm;
                    Ksm[n + 2 * p + half] = num / fmaxf(denom, 1e-8f);
                }
            }
        }
    }
    __syncthreads();

    // ---- phase 2 ----
    const int n = tid;
    float bk = s_beta * Ksm[n];
    float mx = block_reduce_max(bk, red);
    float p = expf(bk - mx);
    float psum = block_reduce_sum(p, red);
    float wc = p / psum;
    float g = s_g;
    float wg = g * wc + (1.f - g) * wpre;
    wgsm[n] = wg;
    __syncthreads();
    float wsh = s_s0 * wgsm[(n + Nn - 1) & (Nn - 1)]
              + s_s1 * wg
              + s_s2 * wgsm[(n + 1) & (Nn - 1)];
    float wsp = powf(wsh, s_gamma);
    float wsum = block_reduce_sum(wsp, red);
    float w = wsp / (wsum + 1e-16f);
    out_w[(size_t)b * Nn + n] = w;
    Ksm[n] = w;
    __syncthreads();

    // ---- phase 3 ----
    const float4 ev = *((const float4*)evec + lane);
    const float4 av = *((const float4*)avec + lane);
    float* __restrict__ omb = out_mem + (size_t)b * Nn * Mm;

    #pragma unroll 1
    for (int j = 8; j < 32; j += 4) {
        const int nr = n_base + j;
        float4 m0 = __ldcs((const float4*)(memb + (size_t)(nr + 0) * Mm) + lane);
        float4 m1 = __ldcs((const float4*)(memb + (size_t)(nr + 1) * Mm) + lane);
        float4 m2 = __ldcs((const float4*)(memb + (size_t)(nr + 2) * Mm) + lane);
        float4 m3 = __ldcs((const float4*)(memb + (size_t)(nr + 3) * Mm) + lane);
        #pragma unroll
        for (int qq = 0; qq < 4; qq++) {
            float4 mv = (qq == 0) ? m0 : (qq == 1) ? m1 : (qq == 2) ? m2 : m3;
            float wn = Ksm[nr + qq];
            float4 r;
            r.x = mv.x * (1.f - wn * ev.x) + wn * av.x;
            r.y = mv.y * (1.f - wn * ev.y) + wn * av.y;
            r.z = mv.z * (1.f - wn * ev.z) + wn * av.z;
            r.w = mv.w * (1.f - wn * ev.w) + wn * av.w;
            __stcs((float4*)(omb + (size_t)(nr + qq) * Mm) + lane, r);
        }
    }
    #pragma unroll 2
    for (int r8 = 0; r8 < 8; r8++) {
        const int nr = n_base + r8;
        float wn = Ksm[nr];
        float4 mv = *((const float4*)(cache + (size_t)(wid * 8 + r8) * Mm) + lane);
        float4 r;
        r.x = mv.x * (1.f - wn * ev.x) + wn * av.x;
        r.y = mv.y * (1.f - wn * ev.y) + wn * av.y;
        r.z = mv.z * (1.f - wn * ev.z) + wn * av.z;
        r.w = mv.w * (1.f - wn * ev.w) + wn * av.w;
        __stcs((float4*)(omb + (size_t)nr * Mm) + lane, r);
    }
}

// ------------------------------------------------------------------
extern "C" void kernel_launch(void* const* d_in, const int* in_sizes, int n_in,
                              void* d_out, int out_size) {
    const float* hid    = (const float*)d_in[0];
    const float* w_pre  = (const float*)d_in[1];
    const float* memory = (const float*)d_in[2];
    const float* W_fc   = (const float*)d_in[3];
    const float* b_fc   = (const float*)d_in[4];
    float* out = (float*)d_out;
    float* out_w   = out;
    float* out_mem = out + (size_t)Bb * Nn;

    const int ntm_smem = (CACHE_ROWS * Mm + Nn + Nn + Mm + Mm + Mm + 32) * 4;
    static bool attr_set = false;
    if (!attr_set) {
        cudaFuncSetAttribute(ntm_fused, cudaFuncAttributeMaxDynamicSharedMemorySize,
                             ntm_smem);
        attr_set = true;
    }

    fc_mma<<<dim3(Bb / BMt, PODIM / BNt, KS), 256>>>(hid, W_fc);
    ntm_fused<<<Bb, 512, ntm_smem>>>(w_pre, memory, b_fc, out_w, out_mem);
}